// round 1
// baseline (speedup 1.0000x reference)
#include <cuda_runtime.h>
#include <cuda_bf16.h>
#include <math.h>

// Problem constants (fixed shapes: B=1, C=8, H=120, W=160, skip=8)
#define HWSZ   19200
#define IMW    160
#define IMH    120
#define NPIX   2400      // sampled voting pixels (HW / 8)
#define NCH    10        // ceil(2400 / 256) chunks in prep
#define NPT    10        // pixels per thread in prep
#define NSPLIT 4         // pixel-range splits in vote kernel
#define NCOBJ  7         // object classes 1..7 (class 0 = background, never votes)

// ---- scratch (static device globals; no allocation) ----
__device__ float4 g_pxy[NPIX];          // xs, ys, nx, ny (compact, class-grouped)
__device__ float  g_pdep[NPIX];         // exp(vz)
__device__ int    g_off[8];             // g_off[i] = start of class i+1 (i=0..6), g_off[7] = total
__device__ float  g_votes[NSPLIT * NCOBJ * HWSZ];
__device__ float  g_dsum [NSPLIT * NCOBJ * HWSZ];

// ============================================================================
// Kernel 1: per-pixel prep + deterministic class-grouped compaction
// ============================================================================
__global__ void prep_kernel(const int* __restrict__ labels,
                            const int* __restrict__ masks,
                            const float* __restrict__ vp)
{
    const int tid  = threadIdx.x;        // 256 threads
    const int lane = tid & 31;
    const int warp = tid >> 5;           // 8 warps

    __shared__ int s_wcnt[8][8];         // [warp][class]
    __shared__ int s_ccnt[NCH][8];       // per-chunk class counts -> exclusive bases
    __shared__ int s_start[8];           // running class start offsets

    float4 rec[NPT];
    float  depr[NPT];
    int    clsr[NPT];
    int    rankr[NPT];

    const unsigned below = (1u << lane) - 1u;

    #pragma unroll
    for (int k = 0; k < NPT; k++) {
        int i = k * 256 + tid;
        int c = 0;
        float4 r = make_float4(0.f, 0.f, 0.f, 0.f);
        float dep = 0.f;
        if (i < NPIX) {
            int idx = i * 8;
            int lab = labels[idx];
            int msk = masks[idx];
            if (msk > 0 && lab > 0) {
                c = lab;
                float xs = (float)(idx % IMW);
                float ys = (float)(idx / IMW);
                float vx = vp[(lab * 3 + 0) * HWSZ + idx];
                float vy = vp[(lab * 3 + 1) * HWSZ + idx];
                float vz = vp[(lab * 3 + 2) * HWSZ + idx];
                float nrm = sqrtf(vx * vx + vy * vy) + 1e-6f;
                r = make_float4(xs, ys, vx / nrm, vy / nrm);
                dep = expf(vz);
            }
        }
        clsr[k] = c; rec[k] = r; depr[k] = dep;

        // deterministic stable rank within this chunk via ballots
        int myrank = 0;
        #pragma unroll
        for (int cc = 1; cc < 8; cc++) {
            unsigned bal = __ballot_sync(0xFFFFFFFFu, c == cc);
            if (c == cc) myrank = __popc(bal & below);
            if (lane == 0) s_wcnt[warp][cc] = __popc(bal);
        }
        __syncthreads();
        if (c > 0) {
            int base = 0;
            #pragma unroll
            for (int w = 0; w < 8; w++)
                if (w < warp) base += s_wcnt[w][c];
            myrank += base;
        }
        rankr[k] = myrank;
        if (tid >= 1 && tid < 8) {   // tid == class id
            int t = 0;
            #pragma unroll
            for (int w = 0; w < 8; w++) t += s_wcnt[w][tid];
            s_ccnt[k][tid] = t;
        }
        __syncthreads();
    }

    // tiny serial scan: chunk-exclusive bases + class starts
    if (tid == 0) {
        int tot[8];
        for (int cc = 1; cc < 8; cc++) {
            int run = 0;
            for (int k = 0; k < NCH; k++) {
                int t = s_ccnt[k][cc];
                s_ccnt[k][cc] = run;
                run += t;
            }
            tot[cc] = run;
        }
        int off = 0;
        for (int cc = 1; cc < 8; cc++) {
            s_start[cc] = off;
            g_off[cc - 1] = off;
            off += tot[cc];
        }
        g_off[7] = off;
    }
    __syncthreads();

    // placement (deterministic slots)
    #pragma unroll
    for (int k = 0; k < NPT; k++) {
        int c = clsr[k];
        if (c > 0) {
            int slot = s_start[c] + s_ccnt[k][c] + rankr[k];
            g_pxy[slot]  = rec[k];
            g_pdep[slot] = depr[k];
        }
    }
}

// ============================================================================
// Kernel 2: Hough voting. One thread per cell, class loop fully unrolled,
// pixel range split across blockIdx.y for occupancy.
// ============================================================================
__global__ void __launch_bounds__(256) vote_kernel()
{
    __shared__ float4 sxy[NPIX];
    __shared__ float  sdep[NPIX];
    __shared__ int    soff[8];

    const int tid = threadIdx.x;      // 256
    if (tid < 8) soff[tid] = g_off[tid];
    __syncthreads();
    const int tot = soff[7];
    for (int i = tid; i < tot; i += 256) {
        sxy[i]  = g_pxy[i];
        sdep[i] = g_pdep[i];
    }
    __syncthreads();

    const int loc   = blockIdx.x * 256 + tid;     // 0..19199
    const int split = blockIdx.y;                 // 0..NSPLIT-1
    const float gx = (float)(loc % IMW);
    const float gy = (float)(loc / IMW);

    float votes[NCOBJ], dsum[NCOBJ];

    #pragma unroll
    for (int ci = 0; ci < NCOBJ; ci++) {
        const int a = soff[ci];
        const int b = soff[ci + 1];
        const int len = b - a;
        const int p0 = a + (len * split) / NSPLIT;
        const int p1 = a + (len * (split + 1)) / NSPLIT;
        float v = 0.f, ds = 0.f;
        #pragma unroll 4
        for (int p = p0; p < p1; p++) {
            float4 q = sxy[p];
            float dx = gx - q.x;
            float dy = gy - q.y;
            float dot = dx * q.z + dy * q.w;
            float d2  = dx * dx + dy * dy;
            // dot > 0.9*sqrt(d2)  <=>  dot > 0 && dot^2 > 0.81*d2
            if (dot > 0.f && dot * dot > (0.9f * 0.9f) * d2) {
                v  += 1.f;
                ds += sdep[p];
            }
        }
        votes[ci] = v;
        dsum[ci]  = ds;
    }

    #pragma unroll
    for (int ci = 0; ci < NCOBJ; ci++) {
        g_votes[(split * NCOBJ + ci) * HWSZ + loc] = votes[ci];
        g_dsum [(split * NCOBJ + ci) * HWSZ + loc] = dsum[ci];
    }
}

// ============================================================================
// Kernel 3: per-class split-sum + argmax (first-max tie-break) + outputs
// ============================================================================
__global__ void reduce_kernel(const float* __restrict__ extents,
                              const float* __restrict__ poses,
                              const float* __restrict__ meta,
                              float* __restrict__ out)
{
    const int c   = blockIdx.x;    // class 0..7
    const int tid = threadIdx.x;   // 256

    __shared__ float sv[256];
    __shared__ float sd[256];
    __shared__ int   sl[256];

    float bv = -1.f, bd = 0.f;
    int   bl = 0;

    if (c > 0) {
        const int ci = c - 1;
        for (int loc = tid; loc < HWSZ; loc += 256) {
            float v = 0.f, d = 0.f;
            #pragma unroll
            for (int s = 0; s < NSPLIT; s++) {
                v += g_votes[(s * NCOBJ + ci) * HWSZ + loc];
                d += g_dsum [(s * NCOBJ + ci) * HWSZ + loc];
            }
            if (v > bv) { bv = v; bl = loc; bd = d; }   // ascending loc -> first max kept
        }
    } else {
        // class 0 never votes: argmax of all-zeros -> loc 0, vmax 0
        if (tid == 0) { bv = 0.f; bl = 0; bd = 0.f; }
    }

    sv[tid] = bv; sl[tid] = bl; sd[tid] = bd;
    __syncthreads();
    for (int s = 128; s > 0; s >>= 1) {
        if (tid < s) {
            float ov = sv[tid + s];
            int   ol = sl[tid + s];
            if (ov > sv[tid] || (ov == sv[tid] && ol < sl[tid])) {
                sv[tid] = ov; sl[tid] = ol; sd[tid] = sd[tid + s];
            }
        }
        __syncthreads();
    }

    if (tid == 0) {
        const float vmax = sv[0];
        const int   best = sl[0];
        const float dsumv = sd[0];

        const float dbar = dsumv / fmaxf(vmax, 1.f);
        const float cx = (float)(best % IMW);
        const float cy = (float)(best / IMW);
        const float fx = meta[0], px = meta[2], fy = meta[4], py = meta[5];
        const float e0 = extents[c * 3 + 0];
        const float e1 = extents[c * 3 + 1];
        const float e2 = extents[c * 3 + 2];
        const float diag = sqrtf(e0 * e0 + e1 * e1 + e2 * e2);
        const float safe = fmaxf(dbar, 1e-6f);
        const float bw = diag * fx / safe;
        const float bh = diag * fy / safe;
        const float nv = (c > 0) ? (float)(g_off[c] - ((c == 1) ? 0 : g_off[c - 1]))
                                 : 0.f;
        const float score = vmax / fmaxf(nv, 1.f);

        float* box = out + c * 7;
        box[0] = 0.f;                 // batch index
        box[1] = (float)c;            // class index
        box[2] = cx - bw * 0.5f;
        box[3] = cy - bh * 0.5f;
        box[4] = cx + bw * 0.5f;
        box[5] = cy + bh * 0.5f;
        box[6] = score;

        float* pp = out + 56 + c * 7;
        pp[0] = poses[c * 7 + 0];
        pp[1] = poses[c * 7 + 1];
        pp[2] = poses[c * 7 + 2];
        pp[3] = poses[c * 7 + 3];
        pp[4] = (cx - px) * dbar / fmaxf(fx, 1e-6f);
        pp[5] = (cy - py) * dbar / fmaxf(fy, 1e-6f);
        pp[6] = dbar;
    }
}

// ============================================================================
extern "C" void kernel_launch(void* const* d_in, const int* in_sizes, int n_in,
                              void* d_out, int out_size)
{
    const int*   labels  = (const int*)d_in[0];
    const int*   masks   = (const int*)d_in[1];
    const float* vp      = (const float*)d_in[2];
    const float* extents = (const float*)d_in[3];
    const float* poses   = (const float*)d_in[4];
    const float* meta    = (const float*)d_in[5];
    float* out = (float*)d_out;

    prep_kernel<<<1, 256>>>(labels, masks, vp);
    vote_kernel<<<dim3(HWSZ / 256, NSPLIT), 256>>>();
    reduce_kernel<<<8, 256>>>(extents, poses, meta, out);
}

// round 2
// speedup vs baseline: 1.1791x; 1.1791x over previous
#include <cuda_runtime.h>
#include <cuda_bf16.h>
#include <math.h>

#define HWSZ   19200
#define IMW    160
#define NPIX   2400
#define NBLKX  75          // 19200 / 256 cell blocks
#define NCOBJ  7           // object classes 1..7

typedef unsigned long long ull;

// ---------------- packed f32x2 helpers ----------------
__device__ __forceinline__ ull pk2(float lo, float hi) {
    ull r; asm("mov.b64 %0, {%1, %2};" : "=l"(r) : "f"(lo), "f"(hi)); return r;
}
__device__ __forceinline__ void up2(ull v, float& lo, float& hi) {
    asm("mov.b64 {%0, %1}, %2;" : "=f"(lo), "=f"(hi) : "l"(v));
}
__device__ __forceinline__ ull add2(ull a, ull b) {
    ull r; asm("add.rn.f32x2 %0, %1, %2;" : "=l"(r) : "l"(a), "l"(b)); return r;
}
__device__ __forceinline__ ull mul2(ull a, ull b) {
    ull r; asm("mul.rn.f32x2 %0, %1, %2;" : "=l"(r) : "l"(a), "l"(b)); return r;
}
__device__ __forceinline__ ull fma2(ull a, ull b, ull c) {
    ull r; asm("fma.rn.f32x2 %0, %1, %2, %3;" : "=l"(r) : "l"(a), "l"(b), "l"(c)); return r;
}

// ---------------- scratch ----------------
// pair p of class c: g_xy[c][4p..4p+3] = (-xs0,-xs1,-ys0,-ys1)
//                    g_nn[c][4p..4p+3] = (nx'0,nx'1,ny'0,ny'1)   nx' = nx/0.9
//                    g_dp[c][2p..2p+1] = (dep0, dep1)
__device__ __align__(16) float g_xy[NCOBJ][4800];
__device__ __align__(16) float g_nn[NCOBJ][4800];
__device__ __align__(8)  float g_dp[NCOBJ][2400];
__device__ int   g_cnt[NCOBJ];
__device__ int   g_npair[NCOBJ];
__device__ int   g_pv[NCOBJ * NBLKX];
__device__ int   g_pl[NCOBJ * NBLKX];
__device__ float g_pds[NCOBJ * NBLKX];

struct P4 { ull a, b; };

// ============================================================================
// Kernel 1: prep — batched loads, warp-per-class ballot compaction
// ============================================================================
__global__ void __launch_bounds__(256) prep_kernel(const int* __restrict__ labels,
                                                   const int* __restrict__ masks,
                                                   const float* __restrict__ vp)
{
    __shared__ int s_cls[NPIX];
    const int tid = threadIdx.x, lane = tid & 31, warp = tid >> 5;

    // Phase A: batched loads of labels/masks (high MLP), class map to shared
    int labv[10], mskv[10];
    #pragma unroll
    for (int k = 0; k < 10; k++) { int i = k * 256 + tid; labv[k] = (i < NPIX) ? labels[i * 8] : 0; }
    #pragma unroll
    for (int k = 0; k < 10; k++) { int i = k * 256 + tid; mskv[k] = (i < NPIX) ? masks[i * 8] : 0; }
    #pragma unroll
    for (int k = 0; k < 10; k++) {
        int i = k * 256 + tid;
        if (i < NPIX) s_cls[i] = (mskv[k] > 0 && labv[k] > 0) ? labv[k] : 0;
    }
    __syncthreads();

    // Phase B: warp w compacts class w+1 (index order preserved => deterministic)
    if (warp < NCOBJ) {
        const int myc = warp + 1;
        const unsigned below = (1u << lane) - 1u;
        int base = 0;
        #pragma unroll 5
        for (int it = 0; it < 75; it++) {
            int i = it * 32 + lane;
            bool pred = (s_cls[i] == myc);
            unsigned bal = __ballot_sync(0xFFFFFFFFu, pred);
            if (pred) {
                int slot = base + __popc(bal & below);
                int idx = i * 8;
                float vx = vp[(myc * 3 + 0) * HWSZ + idx];
                float vy = vp[(myc * 3 + 1) * HWSZ + idx];
                float vz = vp[(myc * 3 + 2) * HWSZ + idx];
                float nrm = sqrtf(vx * vx + vy * vy) + 1e-6f;
                float nxp = (vx / nrm) * (1.0f / 0.9f);
                float nyp = (vy / nrm) * (1.0f / 0.9f);
                float xs = (float)(idx % IMW);
                float ys = (float)(idx / IMW);
                int p = slot >> 1, h = slot & 1;
                g_xy[warp][p * 4 + h]     = -xs;
                g_xy[warp][p * 4 + 2 + h] = -ys;
                g_nn[warp][p * 4 + h]     = nxp;
                g_nn[warp][p * 4 + 2 + h] = nyp;
                g_dp[warp][p * 2 + h]     = expf(vz);
            }
            base += __popc(bal);
        }
        // pad to multiple of 8 pixels with never-inlier dummies (nx'=ny'=0 -> dot=0)
        int pad = (base + 7) & ~7;
        for (int s = base + lane; s < pad; s += 32) {
            int p = s >> 1, h = s & 1;
            g_xy[warp][p * 4 + h] = 0.f;  g_xy[warp][p * 4 + 2 + h] = 0.f;
            g_nn[warp][p * 4 + h] = 0.f;  g_nn[warp][p * 4 + 2 + h] = 0.f;
            g_dp[warp][p * 2 + h] = 0.f;
        }
        if (lane == 0) { g_cnt[warp] = base; g_npair[warp] = pad >> 1; }
    }
}

// ============================================================================
// Kernel 2: vote — grid (75 cell-blocks, 7 classes), packed f32x2 inner loop,
// block-local argmax => tiny partials (no votes map in global)
// ============================================================================
__global__ void __launch_bounds__(256) vote_kernel()
{
    __shared__ P4     s_xy[1200];
    __shared__ P4     s_nn[1200];
    __shared__ float2 s_dp[1200];

    const int cls = blockIdx.y;           // 0..6  (class cls+1)
    const int tid = threadIdx.x;
    const int npair = g_npair[cls];       // multiple of 4

    const P4*     gxy = (const P4*)g_xy[cls];
    const P4*     gnn = (const P4*)g_nn[cls];
    const float2* gdp = (const float2*)g_dp[cls];
    for (int i = tid; i < npair; i += 256) { s_xy[i] = gxy[i]; s_nn[i] = gnn[i]; s_dp[i] = gdp[i]; }
    __syncthreads();

    const int loc = blockIdx.x * 256 + tid;
    const float gx = (float)(loc % IMW);
    const float gy = (float)(loc / IMW);
    const ull gx2 = pk2(gx, gx);
    const ull gy2 = pk2(gy, gy);

    int v = 0; float ds = 0.f;
    #pragma unroll 4
    for (int p = 0; p < npair; p++) {
        P4 axy = s_xy[p];                 // (-xs pair, -ys pair)
        P4 ann = s_nn[p];                 // (nx' pair, ny' pair)
        float2 dd = s_dp[p];
        ull dx2  = add2(gx2, axy.a);
        ull dy2  = add2(gy2, axy.b);
        ull dot2 = fma2(dy2, ann.b, mul2(dx2, ann.a));   // dot' = dot/0.9
        ull d22  = fma2(dy2, dy2, mul2(dx2, dx2));       // d2
        ull q2   = mul2(dot2, dot2);
        float dot0, dot1, q0, q1, e0, e1;
        up2(dot2, dot0, dot1); up2(q2, q0, q1); up2(d22, e0, e1);
        // inlier: dot > 0.9*dist  <=>  dot' > 0 && dot'^2 > d2
        if (dot0 > 0.f && q0 > e0) { v++; ds += dd.x; }
        if (dot1 > 0.f && q1 > e1) { v++; ds += dd.y; }
    }

    // block-local argmax (max count, min loc on ties) — reuse smem
    __syncthreads();
    int*   rv = (int*)s_xy;
    int*   rl = (int*)s_nn;
    float* rd = (float*)s_dp;
    rv[tid] = v; rl[tid] = loc; rd[tid] = ds;
    __syncthreads();
    #pragma unroll
    for (int s = 128; s > 0; s >>= 1) {
        if (tid < s) {
            int ov = rv[tid + s], ol = rl[tid + s];
            if (ov > rv[tid] || (ov == rv[tid] && ol < rl[tid])) {
                rv[tid] = ov; rl[tid] = ol; rd[tid] = rd[tid + s];
            }
        }
        __syncthreads();
    }
    if (tid == 0) {
        g_pv [cls * NBLKX + blockIdx.x] = rv[0];
        g_pl [cls * NBLKX + blockIdx.x] = rl[0];
        g_pds[cls * NBLKX + blockIdx.x] = rd[0];
    }
}

// ============================================================================
// Kernel 3: final — warp-per-class reduction over 75 partials + output math
// ============================================================================
__global__ void __launch_bounds__(256) final_kernel(const float* __restrict__ extents,
                                                    const float* __restrict__ poses,
                                                    const float* __restrict__ meta,
                                                    float* __restrict__ out)
{
    const int tid = threadIdx.x, lane = tid & 31, c = tid >> 5;  // warp == class 0..7

    float vmax = 0.f, dsum = 0.f, nv = 0.f;
    int best = 0;
    if (c > 0) {
        const int ci = c - 1;
        int bc = -1, bl = 0; float bd = 0.f;
        for (int j = lane; j < NBLKX; j += 32) {
            int   vv = g_pv [ci * NBLKX + j];
            int   ll = g_pl [ci * NBLKX + j];
            float dd = g_pds[ci * NBLKX + j];
            if (vv > bc || (vv == bc && ll < bl)) { bc = vv; bl = ll; bd = dd; }
        }
        #pragma unroll
        for (int off = 16; off > 0; off >>= 1) {
            int   ov = __shfl_down_sync(0xFFFFFFFFu, bc, off);
            int   ol = __shfl_down_sync(0xFFFFFFFFu, bl, off);
            float od = __shfl_down_sync(0xFFFFFFFFu, bd, off);
            if (ov > bc || (ov == bc && ol < bl)) { bc = ov; bl = ol; bd = od; }
        }
        vmax = (float)bc; best = bl; dsum = bd;
        nv = (float)g_cnt[ci];
    }
    // class 0: vmax=0, best=0, dsum=0, nv=0 falls through the same math

    if (lane == 0) {
        const float dbar = dsum / fmaxf(vmax, 1.f);
        const float cx = (float)(best % IMW);
        const float cy = (float)(best / IMW);
        const float fx = meta[0], px = meta[2], fy = meta[4], py = meta[5];
        const float e0 = extents[c * 3 + 0];
        const float e1 = extents[c * 3 + 1];
        const float e2 = extents[c * 3 + 2];
        const float diag = sqrtf(e0 * e0 + e1 * e1 + e2 * e2);
        const float safe = fmaxf(dbar, 1e-6f);
        const float bw = diag * fx / safe;
        const float bh = diag * fy / safe;
        const float score = vmax / fmaxf(nv, 1.f);

        float* box = out + c * 7;
        box[0] = 0.f;
        box[1] = (float)c;
        box[2] = cx - bw * 0.5f;
        box[3] = cy - bh * 0.5f;
        box[4] = cx + bw * 0.5f;
        box[5] = cy + bh * 0.5f;
        box[6] = score;

        float* pp = out + 56 + c * 7;
        pp[0] = poses[c * 7 + 0];
        pp[1] = poses[c * 7 + 1];
        pp[2] = poses[c * 7 + 2];
        pp[3] = poses[c * 7 + 3];
        pp[4] = (cx - px) * dbar / fmaxf(fx, 1e-6f);
        pp[5] = (cy - py) * dbar / fmaxf(fy, 1e-6f);
        pp[6] = dbar;
    }
}

// ============================================================================
extern "C" void kernel_launch(void* const* d_in, const int* in_sizes, int n_in,
                              void* d_out, int out_size)
{
    const int*   labels  = (const int*)d_in[0];
    const int*   masks   = (const int*)d_in[1];
    const float* vp      = (const float*)d_in[2];
    const float* extents = (const float*)d_in[3];
    const float* poses   = (const float*)d_in[4];
    const float* meta    = (const float*)d_in[5];
    float* out = (float*)d_out;

    prep_kernel<<<1, 256>>>(labels, masks, vp);
    vote_kernel<<<dim3(NBLKX, NCOBJ), 256>>>();
    final_kernel<<<1, 256>>>(extents, poses, meta, out);
}

// round 3
// speedup vs baseline: 1.3808x; 1.1711x over previous
#include <cuda_runtime.h>
#include <cuda_bf16.h>
#include <math.h>

#define HWSZ   19200
#define IMW    160
#define NPIX   2400
#define NBLKX  75          // 19200 / 256 cell blocks
#define NCOBJ  7           // object classes 1..7

typedef unsigned long long ull;

// ---------------- packed f32x2 helpers ----------------
__device__ __forceinline__ ull pk2(float lo, float hi) {
    ull r; asm("mov.b64 %0, {%1, %2};" : "=l"(r) : "f"(lo), "f"(hi)); return r;
}
__device__ __forceinline__ void up2(ull v, float& lo, float& hi) {
    asm("mov.b64 {%0, %1}, %2;" : "=f"(lo), "=f"(hi) : "l"(v));
}
__device__ __forceinline__ ull add2(ull a, ull b) {
    ull r; asm("add.rn.f32x2 %0, %1, %2;" : "=l"(r) : "l"(a), "l"(b)); return r;
}
__device__ __forceinline__ ull mul2(ull a, ull b) {
    ull r; asm("mul.rn.f32x2 %0, %1, %2;" : "=l"(r) : "l"(a), "l"(b)); return r;
}
__device__ __forceinline__ ull fma2(ull a, ull b, ull c) {
    ull r; asm("fma.rn.f32x2 %0, %1, %2, %3;" : "=l"(r) : "l"(a), "l"(b), "l"(c)); return r;
}

// ---------------- scratch ----------------
__device__ __align__(16) float4 g_rec[NPIX];     // xs, ys, nx', ny'  (staging, pixel order)
__device__ float  g_dep[NPIX];                   // exp(vz)
__device__ int    g_cls[NPIX];                   // effective class (0 = no vote)

// pair p of class c: g_xy[c][4p..4p+3] = (-xs0,-xs1,-ys0,-ys1)
//                    g_nn[c][4p..4p+3] = (nx'0,nx'1,ny'0,ny'1)   nx' = nx/0.9
//                    g_dp[c][2p..2p+1] = (dep0, dep1)
__device__ __align__(16) float g_xy[NCOBJ][4800];
__device__ __align__(16) float g_nn[NCOBJ][4800];
__device__ __align__(8)  float g_dp[NCOBJ][2400];
__device__ int   g_cnt[NCOBJ];
__device__ int   g_npair[NCOBJ];
__device__ int   g_pv[NCOBJ * NBLKX];
__device__ int   g_pl[NCOBJ * NBLKX];
__device__ float g_pds[NCOBJ * NBLKX];

struct P4 { ull a, b; };

// ============================================================================
// Kernel A: staging — one thread per sampled pixel, all heavy math parallel
// ============================================================================
__global__ void __launch_bounds__(128) stage_kernel(const int* __restrict__ labels,
                                                    const int* __restrict__ masks,
                                                    const float* __restrict__ vp)
{
    const int i = blockIdx.x * 128 + threadIdx.x;
    if (i >= NPIX) return;
    const int idx = i * 8;
    const int lab = labels[idx];
    const int msk = masks[idx];
    const int c = (msk > 0 && lab > 0) ? lab : 0;
    g_cls[i] = c;
    if (c) {
        const float vx = vp[(c * 3 + 0) * HWSZ + idx];
        const float vy = vp[(c * 3 + 1) * HWSZ + idx];
        const float vz = vp[(c * 3 + 2) * HWSZ + idx];
        const float nrm = sqrtf(vx * vx + vy * vy) + 1e-6f;
        const float nxp = (vx / nrm) * (1.0f / 0.9f);
        const float nyp = (vy / nrm) * (1.0f / 0.9f);
        g_rec[i] = make_float4((float)(idx % IMW), (float)(idx / IMW), nxp, nyp);
        g_dep[i] = expf(vz);
    }
}

// ============================================================================
// Kernel B: compaction — warp-per-class ballot loop; gathers hit L2 staging,
// load addresses independent of loop-carried base => pipelined
// ============================================================================
__global__ void __launch_bounds__(256) compact_kernel()
{
    __shared__ int s_cls[NPIX];
    const int tid = threadIdx.x, lane = tid & 31, warp = tid >> 5;

    const int4* gc4 = (const int4*)g_cls;
    int4* sc4 = (int4*)s_cls;
    #pragma unroll
    for (int k = 0; k < 3; k++) {
        int j = k * 256 + tid;
        if (j < NPIX / 4) sc4[j] = gc4[j];
    }
    __syncthreads();

    if (warp < NCOBJ) {
        const int myc = warp + 1;
        const unsigned below = (1u << lane) - 1u;
        int base = 0;
        #pragma unroll 5
        for (int it = 0; it < 75; it++) {
            const int i = it * 32 + lane;
            const bool pred = (s_cls[i] == myc);
            const unsigned bal = __ballot_sync(0xFFFFFFFFu, pred);
            if (pred) {
                const float4 r = g_rec[i];      // L2 hit (staging just written)
                const float  d = g_dep[i];
                const int slot = base + __popc(bal & below);
                const int p = slot >> 1, h = slot & 1;
                g_xy[warp][p * 4 + h]     = -r.x;
                g_xy[warp][p * 4 + 2 + h] = -r.y;
                g_nn[warp][p * 4 + h]     = r.z;
                g_nn[warp][p * 4 + 2 + h] = r.w;
                g_dp[warp][p * 2 + h]     = d;
            }
            base += __popc(bal);
        }
        // pad to multiple of 8 pixels with never-inlier dummies (nx'=ny'=0 -> dot=0)
        const int pad = (base + 7) & ~7;
        for (int s = base + lane; s < pad; s += 32) {
            const int p = s >> 1, h = s & 1;
            g_xy[warp][p * 4 + h] = 0.f;  g_xy[warp][p * 4 + 2 + h] = 0.f;
            g_nn[warp][p * 4 + h] = 0.f;  g_nn[warp][p * 4 + 2 + h] = 0.f;
            g_dp[warp][p * 2 + h] = 0.f;
        }
        if (lane == 0) { g_cnt[warp] = base; g_npair[warp] = pad >> 1; }
    }
}

// ============================================================================
// Kernel C: vote — grid (75 cell-blocks, 7 classes), packed f32x2 inner loop,
// block-local argmax => tiny partials
// ============================================================================
__global__ void __launch_bounds__(256) vote_kernel()
{
    __shared__ P4     s_xy[1200];
    __shared__ P4     s_nn[1200];
    __shared__ float2 s_dp[1200];

    const int cls = blockIdx.y;           // 0..6  (class cls+1)
    const int tid = threadIdx.x;
    const int npair = g_npair[cls];       // multiple of 4

    const P4*     gxy = (const P4*)g_xy[cls];
    const P4*     gnn = (const P4*)g_nn[cls];
    const float2* gdp = (const float2*)g_dp[cls];
    for (int i = tid; i < npair; i += 256) { s_xy[i] = gxy[i]; s_nn[i] = gnn[i]; s_dp[i] = gdp[i]; }
    __syncthreads();

    const int loc = blockIdx.x * 256 + tid;
    const float gx = (float)(loc % IMW);
    const float gy = (float)(loc / IMW);
    const ull gx2 = pk2(gx, gx);
    const ull gy2 = pk2(gy, gy);

    int v = 0; float ds = 0.f;
    #pragma unroll 4
    for (int p = 0; p < npair; p++) {
        P4 axy = s_xy[p];                 // (-xs pair, -ys pair)
        P4 ann = s_nn[p];                 // (nx' pair, ny' pair)
        float2 dd = s_dp[p];
        ull dx2  = add2(gx2, axy.a);
        ull dy2  = add2(gy2, axy.b);
        ull dot2 = fma2(dy2, ann.b, mul2(dx2, ann.a));   // dot' = dot/0.9
        ull d22  = fma2(dy2, dy2, mul2(dx2, dx2));       // d2
        ull q2   = mul2(dot2, dot2);
        float dot0, dot1, q0, q1, e0, e1;
        up2(dot2, dot0, dot1); up2(q2, q0, q1); up2(d22, e0, e1);
        // inlier: dot > 0.9*dist  <=>  dot' > 0 && dot'^2 > d2
        if (dot0 > 0.f && q0 > e0) { v++; ds += dd.x; }
        if (dot1 > 0.f && q1 > e1) { v++; ds += dd.y; }
    }

    // block-local argmax (max count, min loc on ties) — reuse smem
    __syncthreads();
    int*   rv = (int*)s_xy;
    int*   rl = (int*)s_nn;
    float* rd = (float*)s_dp;
    rv[tid] = v; rl[tid] = loc; rd[tid] = ds;
    __syncthreads();
    #pragma unroll
    for (int s = 128; s > 0; s >>= 1) {
        if (tid < s) {
            int ov = rv[tid + s], ol = rl[tid + s];
            if (ov > rv[tid] || (ov == rv[tid] && ol < rl[tid])) {
                rv[tid] = ov; rl[tid] = ol; rd[tid] = rd[tid + s];
            }
        }
        __syncthreads();
    }
    if (tid == 0) {
        g_pv [cls * NBLKX + blockIdx.x] = rv[0];
        g_pl [cls * NBLKX + blockIdx.x] = rl[0];
        g_pds[cls * NBLKX + blockIdx.x] = rd[0];
    }
}

// ============================================================================
// Kernel D: final — warp-per-class reduction over 75 partials + output math
// ============================================================================
__global__ void __launch_bounds__(256) final_kernel(const float* __restrict__ extents,
                                                    const float* __restrict__ poses,
                                                    const float* __restrict__ meta,
                                                    float* __restrict__ out)
{
    const int tid = threadIdx.x, lane = tid & 31, c = tid >> 5;  // warp == class 0..7

    float vmax = 0.f, dsum = 0.f, nv = 0.f;
    int best = 0;
    if (c > 0) {
        const int ci = c - 1;
        int bc = -1, bl = 0; float bd = 0.f;
        for (int j = lane; j < NBLKX; j += 32) {
            int   vv = g_pv [ci * NBLKX + j];
            int   ll = g_pl [ci * NBLKX + j];
            float dd = g_pds[ci * NBLKX + j];
            if (vv > bc || (vv == bc && ll < bl)) { bc = vv; bl = ll; bd = dd; }
        }
        #pragma unroll
        for (int off = 16; off > 0; off >>= 1) {
            int   ov = __shfl_down_sync(0xFFFFFFFFu, bc, off);
            int   ol = __shfl_down_sync(0xFFFFFFFFu, bl, off);
            float od = __shfl_down_sync(0xFFFFFFFFu, bd, off);
            if (ov > bc || (ov == bc && ol < bl)) { bc = ov; bl = ol; bd = od; }
        }
        vmax = (float)bc; best = bl; dsum = bd;
        nv = (float)g_cnt[ci];
    }
    // class 0: vmax=0, best=0, dsum=0, nv=0 falls through the same math

    if (lane == 0) {
        const float dbar = dsum / fmaxf(vmax, 1.f);
        const float cx = (float)(best % IMW);
        const float cy = (float)(best / IMW);
        const float fx = meta[0], px = meta[2], fy = meta[4], py = meta[5];
        const float e0 = extents[c * 3 + 0];
        const float e1 = extents[c * 3 + 1];
        const float e2 = extents[c * 3 + 2];
        const float diag = sqrtf(e0 * e0 + e1 * e1 + e2 * e2);
        const float safe = fmaxf(dbar, 1e-6f);
        const float bw = diag * fx / safe;
        const float bh = diag * fy / safe;
        const float score = vmax / fmaxf(nv, 1.f);

        float* box = out + c * 7;
        box[0] = 0.f;
        box[1] = (float)c;
        box[2] = cx - bw * 0.5f;
        box[3] = cy - bh * 0.5f;
        box[4] = cx + bw * 0.5f;
        box[5] = cy + bh * 0.5f;
        box[6] = score;

        float* pp = out + 56 + c * 7;
        pp[0] = poses[c * 7 + 0];
        pp[1] = poses[c * 7 + 1];
        pp[2] = poses[c * 7 + 2];
        pp[3] = poses[c * 7 + 3];
        pp[4] = (cx - px) * dbar / fmaxf(fx, 1e-6f);
        pp[5] = (cy - py) * dbar / fmaxf(fy, 1e-6f);
        pp[6] = dbar;
    }
}

// ============================================================================
extern "C" void kernel_launch(void* const* d_in, const int* in_sizes, int n_in,
                              void* d_out, int out_size)
{
    const int*   labels  = (const int*)d_in[0];
    const int*   masks   = (const int*)d_in[1];
    const float* vp      = (const float*)d_in[2];
    const float* extents = (const float*)d_in[3];
    const float* poses   = (const float*)d_in[4];
    const float* meta    = (const float*)d_in[5];
    float* out = (float*)d_out;

    stage_kernel<<<(NPIX + 127) / 128, 128>>>(labels, masks, vp);
    compact_kernel<<<1, 256>>>();
    vote_kernel<<<dim3(NBLKX, NCOBJ), 256>>>();
    final_kernel<<<1, 256>>>(extents, poses, meta, out);
}